// round 14
// baseline (speedup 1.0000x reference)
#include <cuda_runtime.h>
#include <cuda_fp16.h>
#include <math.h>
#include <stdint.h>

#define NN 50000
#define EE 800000
#define DD 64
#define HH 8

// ---------------- scratch (static device globals; no allocation) ----------------
__device__ float  g_h[NN * DD];      // node features fp32 (layer input / ping)
__device__ __half g_hph[NN * DD];    // projected features, half (edge gather)
__device__ float  g_ai[NN * HH];     // per-node att dot, dst half (fp32)
__device__ __half g_ajh[NN * HH];    // per-node att dot, src half (fp16)
__device__ int    g_deg[NN];         // zero at entry (re-zeroed by input GEMM)
__device__ int    g_rowptr[NN];      // after scatter: rowptr[n] == orig rowptr[n+1]
__device__ int    g_csrc[EE];        // CSR-by-dst: source node per slot
__device__ __half g_wext[6 * 2 * 64 * 80];  // pre-split [Wh;Wl] of [W | W@Ai | W@Aj]
__device__ float  g_biatt[6 * 16];   // bias·att constants per layer (ai 0-7, aj 8-15)

// ---------------- CSR build ----------------
__global__ void k_hist(const int* __restrict__ dst) {
    int e = blockIdx.x * blockDim.x + threadIdx.x;
    if (e < EE) atomicAdd(&g_deg[dst[e]], 1);
}

// single merged scan: each block redundantly computes its carry (sum of deg
// before its chunk), then does a local 1024-wide scan and writes rowptr.
__global__ void __launch_bounds__(1024) k_scan() {
    __shared__ int ws[32];
    __shared__ int red[32];
    int tidx = threadIdx.x;
    int lane = tidx & 31, w = tidx >> 5;
    int limit = blockIdx.x << 10;
    int acc = 0;
    for (int i = tidx; i < limit; i += 1024) acc += g_deg[i];
#pragma unroll
    for (int o = 16; o > 0; o >>= 1) acc += __shfl_xor_sync(0xffffffffu, acc, o);
    if (lane == 0) red[w] = acc;
    int i = limit + tidx;
    int x = (i < NN) ? g_deg[i] : 0;
    int v = x;
#pragma unroll
    for (int o = 1; o < 32; o <<= 1) {
        int t = __shfl_up_sync(0xffffffffu, v, o);
        if (lane >= o) v += t;
    }
    if (lane == 31) ws[w] = v;
    __syncthreads();
    if (w == 0) {
        int t = ws[lane];
#pragma unroll
        for (int o = 1; o < 32; o <<= 1) {
            int u = __shfl_up_sync(0xffffffffu, t, o);
            if (lane >= o) t += u;
        }
        ws[lane] = t;
        int r = red[lane];
#pragma unroll
        for (int o = 16; o > 0; o >>= 1) r += __shfl_xor_sync(0xffffffffu, r, o);
        if (lane == 0) red[0] = r;
    }
    __syncthreads();
    int carry = red[0];
    int off = (w > 0) ? ws[w - 1] : 0;
    if (i < NN) g_rowptr[i] = carry + off + v - x;   // exclusive global prefix
}

__global__ void k_scatter(const int* __restrict__ src, const int* __restrict__ dst) {
    int e = blockIdx.x * blockDim.x + threadIdx.x;
    if (e < EE) {
        int pos = atomicAdd(&g_rowptr[dst[e]], 1);
        g_csrc[pos] = src[e];
    }
}

// ---------------- per-call weight preprocessing ----------------
// Builds Wext_l = [W_l | W_l@Ai_l | W_l@Aj_l] (64x80 fp32), splits to fp16
// hi/lo (Markidis), and the bias-att constants b·att. Layer 0 = input
// embedding (att cols zero).
__global__ void k_wsplit(const float* __restrict__ W_in,
                         const float* __restrict__ lin_w,
                         const float* __restrict__ lin_b,
                         const float* __restrict__ att) {
    int idx = blockIdx.x * blockDim.x + threadIdx.x;
    if (idx < 6 * 16) {
        int l = idx >> 4, t = idx & 15;
        float v = 0.f;
        if (l >= 1) {
            int h = t & 7;
            const float* b = lin_b + (l - 1) * 64 + h * 8;
            const float* a = att + (l - 1) * 128 + h * 16 + ((t & 8) ? 8 : 0);
            float s = 0.f;
#pragma unroll
            for (int q = 0; q < 8; q++) s += b[q] * a[q];
            v = s;
        }
        g_biatt[idx] = v;
    }
    if (idx >= 6 * 64 * 80) return;
    int l = idx / (64 * 80);
    int rc = idx % (64 * 80);
    int r = rc / 80, c = rc % 80;
    const float* W = (l == 0) ? W_in : (lin_w + (l - 1) * 4096);
    float v;
    if (c < 64) {
        v = W[r * 64 + c];
    } else if (l == 0) {
        v = 0.f;
    } else {
        int h = (c - 64) & 7;
        const float* a = att + (l - 1) * 128 + h * 16 + (((c - 64) & 8) ? 8 : 0);
        const float* wr = W + r * 64 + h * 8;
        float s = 0.f;
#pragma unroll
        for (int q = 0; q < 8; q++) s += wr[q] * a[q];
        v = s;
    }
    __half hi = __float2half_rn(v);
    __half lo = __float2half_rn(v - __half2float(hi));
    int off = l * 2 * 64 * 80;
    g_wext[off + r * 80 + c] = hi;
    g_wext[off + 64 * 80 + r * 80 + c] = lo;
}

// ---------------- split-fp16 tensor GEMM with fused att columns ----------------
// C[N,80] = A[N,64] @ Wext[64,80], ~fp32 precision via packed-K Markidis:
// As=[Ah|Al] (64x128), Bs=[Wexth;Wextl] (128x80, pre-split in gmem).
// Cols 0-63: hp (+bias); cols 64-71: ai (+b·att_i); cols 72-79: aj (+b·att_j).
__device__ __forceinline__ uint32_t smem_u32(const void* p) {
    return (uint32_t)__cvta_generic_to_shared(p);
}

#define LDSM_X4(r0, r1, r2, r3, addr) \
    asm volatile("ldmatrix.sync.aligned.m8n8.x4.shared.b16 {%0,%1,%2,%3}, [%4];" \
        : "=r"(r0), "=r"(r1), "=r"(r2), "=r"(r3) : "r"(addr))

#define LDSM_X4_T(r0, r1, r2, r3, addr) \
    asm volatile("ldmatrix.sync.aligned.m8n8.x4.trans.shared.b16 {%0,%1,%2,%3}, [%4];" \
        : "=r"(r0), "=r"(r1), "=r"(r2), "=r"(r3) : "r"(addr))

#define MMA16816(c, a0, a1, a2, a3, b0, b1) \
    asm volatile("mma.sync.aligned.m16n8k16.row.col.f32.f16.f16.f32 " \
        "{%0,%1,%2,%3}, {%4,%5,%6,%7}, {%8,%9}, {%0,%1,%2,%3};" \
        : "+f"(c[0]), "+f"(c[1]), "+f"(c[2]), "+f"(c[3]) \
        : "r"(a0), "r"(a1), "r"(a2), "r"(a3), "r"(b0), "r"(b1))

#define SMSA 136  // As row stride in halves (128 + 8 pad)
#define SMSB 88   // Bs row stride in halves (80 + 8 pad)

__device__ __forceinline__ void split8(const float* v, __half* hi, __half* lo) {
#pragma unroll
    for (int q = 0; q < 8; q++) {
        __half h = __float2half_rn(v[q]);
        hi[q] = h;
        lo[q] = __float2half_rn(v[q] - __half2float(h));
    }
}

__global__ void __launch_bounds__(128) k_gemm_e(const float* __restrict__ A,
                                                const __half* __restrict__ wext,
                                                const float* __restrict__ bias,
                                                const float* __restrict__ biatt,
                                                float* __restrict__ Cf,
                                                __half* __restrict__ Ch,
                                                int do_relu, int do_att) {
    __shared__ __half As[64 * SMSA];   // [Ah | Al]
    __shared__ __half Bs[128 * SMSB];  // [Wexth ; Wextl]
    int tid = threadIdx.x;
    int base = blockIdx.x * 64;
    if (do_relu) {                     // reset deg for the NEXT call's histogram
        int gz = blockIdx.x * 128 + tid;
        if (gz < NN) g_deg[gz] = 0;
    }
#pragma unroll
    for (int i = 0; i < 10; i++) {
        int chunk = tid + i * 128;            // 0..1279
        int r = chunk / 10, c8 = (chunk % 10) * 8;
        uint4 v = *(const uint4*)(wext + chunk * 8);
        *(uint4*)(Bs + r * SMSB + c8) = v;
    }
#pragma unroll
    for (int i = 0; i < 4; i++) {
        int chunk = tid + i * 128;            // 0..511
        int r = chunk >> 3, c = (chunk & 7) * 8;
        int gr = base + r;
        float av[8] = {0.f, 0.f, 0.f, 0.f, 0.f, 0.f, 0.f, 0.f};
        if (gr < NN) {
            *(float4*)(av)     = *(const float4*)(A + (size_t)gr * 64 + c);
            *(float4*)(av + 4) = *(const float4*)(A + (size_t)gr * 64 + c + 4);
        }
        __align__(16) __half ah[8], al[8];
        split8(av, ah, al);
        *(uint4*)(As + r * SMSA + c)      = *(uint4*)ah;
        *(uint4*)(As + r * SMSA + c + 64) = *(uint4*)al;
    }
    __syncthreads();

    int warp = tid >> 5, lane = tid & 31;
    int m0 = warp * 16;
    float acc[10][4];
#pragma unroll
    for (int n = 0; n < 10; n++)
#pragma unroll
        for (int q = 0; q < 4; q++) acc[n][q] = 0.f;

    uint32_t aA[8][4];
#pragma unroll
    for (int ka = 0; ka < 8; ka++) {
        int aoff = (m0 + (lane & 15)) * SMSA + ka * 16 + (lane >> 4) * 8;
        LDSM_X4(aA[ka][0], aA[ka][1], aA[ka][2], aA[ka][3], smem_u32(As + aoff));
    }

#pragma unroll
    for (int np = 0; np < 5; np++) {
#pragma unroll
        for (int kk = 0; kk < 4; kk++) {
            uint32_t b0, b1, b2, b3;
            int boff = (kk * 16 + (lane & 15)) * SMSB + np * 16 + (lane >> 4) * 8;
            LDSM_X4_T(b0, b1, b2, b3, smem_u32(Bs + boff));
            MMA16816(acc[2 * np],     aA[kk][0], aA[kk][1], aA[kk][2], aA[kk][3], b0, b1);
            MMA16816(acc[2 * np + 1], aA[kk][0], aA[kk][1], aA[kk][2], aA[kk][3], b2, b3);
            MMA16816(acc[2 * np],     aA[kk + 4][0], aA[kk + 4][1], aA[kk + 4][2], aA[kk + 4][3], b0, b1);
            MMA16816(acc[2 * np + 1], aA[kk + 4][0], aA[kk + 4][1], aA[kk + 4][2], aA[kk + 4][3], b2, b3);
        }
#pragma unroll
        for (int kk = 0; kk < 4; kk++) {
            uint32_t b0, b1, b2, b3;
            int boff = ((kk + 4) * 16 + (lane & 15)) * SMSB + np * 16 + (lane >> 4) * 8;
            LDSM_X4_T(b0, b1, b2, b3, smem_u32(Bs + boff));
            MMA16816(acc[2 * np],     aA[kk][0], aA[kk][1], aA[kk][2], aA[kk][3], b0, b1);
            MMA16816(acc[2 * np + 1], aA[kk][0], aA[kk][1], aA[kk][2], aA[kk][3], b2, b3);
        }
    }

    int qr = lane >> 2, qc = (lane & 3) * 2;
    int r0 = base + m0 + qr, r1 = r0 + 8;
#pragma unroll
    for (int n = 0; n < 8; n++) {
        int col = n * 8 + qc;
        float2 bb = *(const float2*)(bias + col);
        float x0 = acc[n][0] + bb.x, y0 = acc[n][1] + bb.y;
        float x1 = acc[n][2] + bb.x, y1 = acc[n][3] + bb.y;
        if (do_att) {
            if (r0 < NN) *(__half2*)(Ch + (size_t)r0 * 64 + col) = __floats2half2_rn(x0, y0);
            if (r1 < NN) *(__half2*)(Ch + (size_t)r1 * 64 + col) = __floats2half2_rn(x1, y1);
        } else {
            if (do_relu) {
                x0 = fmaxf(x0, 0.f); y0 = fmaxf(y0, 0.f);
                x1 = fmaxf(x1, 0.f); y1 = fmaxf(y1, 0.f);
            }
            if (r0 < NN) *(float2*)(Cf + (size_t)r0 * 64 + col) = make_float2(x0, y0);
            if (r1 < NN) *(float2*)(Cf + (size_t)r1 * 64 + col) = make_float2(x1, y1);
        }
    }
    if (do_att) {
        float bi0 = biatt[qc],     bi1 = biatt[qc + 1];
        float bj0 = biatt[8 + qc], bj1 = biatt[8 + qc + 1];
        if (r0 < NN) {
            *(float2*)(g_ai + r0 * 8 + qc) = make_float2(acc[8][0] + bi0, acc[8][1] + bi1);
            *(__half2*)(g_ajh + r0 * 8 + qc) = __floats2half2_rn(acc[9][0] + bj0, acc[9][1] + bj1);
        }
        if (r1 < NN) {
            *(float2*)(g_ai + r1 * 8 + qc) = make_float2(acc[8][2] + bi0, acc[8][3] + bi1);
            *(__half2*)(g_ajh + r1 * 8 + qc) = __floats2half2_rn(acc[9][2] + bj0, acc[9][3] + bj1);
        }
    }
}

// ---------------- fused edge softmax + aggregation + ELU + LayerNorm ----------------
// One warp per destination node. Lane l owns cols (2l,2l+1), head h = l>>2.
// Per 32-edge chunk: phase 1 batches ALL per-lane weight computations (8
// independent aj gathers in flight, then 8 exps); phase 2 accumulates features
// with a one-group-ahead software pipeline (~8 hp gathers in flight).
__global__ void __launch_bounds__(256) k_edge(const float* __restrict__ ob,
                                              const float* __restrict__ lg,
                                              const float* __restrict__ lb,
                                              float* __restrict__ out) {
    int n = (blockIdx.x * blockDim.x + threadIdx.x) >> 5;
    int lane = threadIdx.x & 31;
    if (n >= NN) return;
    // post-scatter rowptr is shifted: rp[n] == original rowptr[n+1]
    int e0 = (n == 0) ? 0 : __ldg(&g_rowptr[n - 1]);
    int e1 = __ldg(&g_rowptr[n]);
    int h = lane >> 2;
    int sub = lane & 3;
    int qb = lane & ~3;
    float aih = __ldg(&g_ai[n * 8 + h]);

    float s = 0.f, ax = 0.f, ay = 0.f;
    const __half2* hp2 = (const __half2*)g_hph;
    for (int cb = e0; cb < e1; cb += 32) {
        int idx = cb + lane;
        int pre = (idx < e1) ? __ldg(&g_csrc[idx]) : 0;
        int cnt = min(32, e1 - cb);
        int ng = (cnt + 3) >> 2;

        // ---- phase 1: per-lane softmax weights, one per group ----
        int   msrc[8];
        __half ajl[8];
        float wv[8];
#pragma unroll
        for (int g = 0; g < 8; g++) {
            if (g >= ng) break;
            msrc[g] = __shfl_sync(0xffffffffu, pre, g * 4 + sub);
        }
#pragma unroll
        for (int g = 0; g < 8; g++) {
            if (g >= ng) break;
            ajl[g] = __ldg(&g_ajh[msrc[g] * 8 + h]);
        }
#pragma unroll
        for (int g = 0; g < 8; g++) {
            if (g >= ng) break;
            float a = aih + __half2float(ajl[g]);
            a = fmaxf(a, 0.2f * a);           // leaky_relu(0.2)
            wv[g] = (g * 4 + sub < cnt) ? __expf(a) : 0.f;
        }

        // ---- phase 2: feature gathers, one group ahead ----
        float2 v0, v1, v2, v3;
        {
            int s0 = __shfl_sync(0xffffffffu, pre, 0);
            int s1 = __shfl_sync(0xffffffffu, pre, 1);
            int s2 = __shfl_sync(0xffffffffu, pre, 2);
            int s3 = __shfl_sync(0xffffffffu, pre, 3);
            v0 = __half22float2(__ldg(&hp2[(unsigned)(s0 * 32 + lane)]));
            v1 = __half22float2(__ldg(&hp2[(unsigned)(s1 * 32 + lane)]));
            v2 = __half22float2(__ldg(&hp2[(unsigned)(s2 * 32 + lane)]));
            v3 = __half22float2(__ldg(&hp2[(unsigned)(s3 * 32 + lane)]));
        }
#pragma unroll
        for (int g = 0; g < 8; g++) {
            if (g >= ng) break;
            float2 n0 = make_float2(0.f, 0.f), n1 = n0, n2 = n0, n3 = n0;
            if (g + 1 < ng) {
                int s0 = __shfl_sync(0xffffffffu, pre, g * 4 + 4);
                int s1 = __shfl_sync(0xffffffffu, pre, g * 4 + 5);
                int s2 = __shfl_sync(0xffffffffu, pre, g * 4 + 6);
                int s3 = __shfl_sync(0xffffffffu, pre, g * 4 + 7);
                n0 = __half22float2(__ldg(&hp2[(unsigned)(s0 * 32 + lane)]));
                n1 = __half22float2(__ldg(&hp2[(unsigned)(s1 * 32 + lane)]));
                n2 = __half22float2(__ldg(&hp2[(unsigned)(s2 * 32 + lane)]));
                n3 = __half22float2(__ldg(&hp2[(unsigned)(s3 * 32 + lane)]));
            }
            float w0 = __shfl_sync(0xffffffffu, wv[g], qb);
            float w1 = __shfl_sync(0xffffffffu, wv[g], qb + 1);
            float w2 = __shfl_sync(0xffffffffu, wv[g], qb + 2);
            float w3 = __shfl_sync(0xffffffffu, wv[g], qb + 3);
            s += w0 + w1 + w2 + w3;
            ax += v0.x * w0 + v1.x * w1 + v2.x * w2 + v3.x * w3;
            ay += v0.y * w0 + v1.y * w1 + v2.y * w2 + v3.y * w3;
            v0 = n0; v1 = n1; v2 = n2; v3 = n3;
        }
    }

    float inv = 1.f / (s + 1e-16f);
    float vx = ax * inv + ob[2 * lane];
    float vy = ay * inv + ob[2 * lane + 1];
    vx = vx > 0.f ? vx : expm1f(vx);          // ELU
    vy = vy > 0.f ? vy : expm1f(vy);

    float sum = vx + vy, sq = vx * vx + vy * vy;
#pragma unroll
    for (int o = 16; o > 0; o >>= 1) {
        sum += __shfl_xor_sync(0xffffffffu, sum, o);
        sq  += __shfl_xor_sync(0xffffffffu, sq, o);
    }
    float mu = sum * (1.f / 64.f);
    float var = sq * (1.f / 64.f) - mu * mu;
    float rstd = rsqrtf(var + 1e-5f);
    float2 o2;
    o2.x = (vx - mu) * rstd * lg[2 * lane] + lb[2 * lane];
    o2.y = (vy - mu) * rstd * lg[2 * lane + 1] + lb[2 * lane + 1];
    ((float2*)out)[(size_t)n * 32 + lane] = o2;
}

// ---------------- launch ----------------
extern "C" void kernel_launch(void* const* d_in, const int* in_sizes, int n_in,
                              void* d_out, int out_size) {
    const float* x        = (const float*)d_in[0];
    const int*   ei       = (const int*)  d_in[1];
    const float* W_in     = (const float*)d_in[2];
    const float* b_in     = (const float*)d_in[3];
    const float* lin_w    = (const float*)d_in[4];
    const float* lin_b    = (const float*)d_in[5];
    const float* att      = (const float*)d_in[6];
    const float* out_bias = (const float*)d_in[7];
    const float* ln_g     = (const float*)d_in[8];
    const float* ln_b     = (const float*)d_in[9];
    float* out = (float*)d_out;
    const int* srcp = ei;        // edge_index[0]
    const int* dstp = ei + EE;   // edge_index[1]
    (void)n_in; (void)in_sizes; (void)out_size;

    void* p;
    cudaGetSymbolAddress(&p, g_h);     float*  ph  = (float*)p;
    cudaGetSymbolAddress(&p, g_hph);   __half* phph = (__half*)p;
    cudaGetSymbolAddress(&p, g_wext);  __half* pwx = (__half*)p;
    cudaGetSymbolAddress(&p, g_biatt); float*  pba = (float*)p;

    // weight preprocessing (independent of CSR)
    k_wsplit<<<(6 * 64 * 80 + 255) / 256, 256>>>(W_in, lin_w, lin_b, att);

    // CSR by dst (g_deg is zero at entry; re-zeroed by the input GEMM each call)
    k_hist   <<<(EE + 255) / 256, 256>>>(dstp);
    k_scan   <<<(NN + 1023) / 1024, 1024>>>();
    k_scatter<<<(EE + 255) / 256, 256>>>(srcp, dstp);

    int gblocks = (NN + 63) / 64;
    // input embedding: h = relu(x @ W_in + b_in), fp32 (also zeroes g_deg)
    k_gemm_e<<<gblocks, 128>>>(x, pwx, b_in, pba, ph, nullptr, 1, 0);

    for (int l = 0; l < 5; l++) {
        k_gemm_e<<<gblocks, 128>>>(ph, pwx + (l + 1) * 2 * 64 * 80,
                                   lin_b + l * 64, pba + (l + 1) * 16,
                                   nullptr, phph, 0, 1);
        k_edge<<<(NN + 7) / 8, 256>>>(out_bias + l * 64, ln_g + l * 64, ln_b + l * 64,
                                      (l == 4) ? out : ph);
    }
}

// round 16
// speedup vs baseline: 1.2353x; 1.2353x over previous
#include <cuda_runtime.h>
#include <cuda_fp16.h>
#include <math.h>
#include <stdint.h>

#define NN 50000
#define EE 800000
#define DD 64
#define HH 8

// ---------------- scratch (static device globals; no allocation) ----------------
__device__ float  g_h[NN * DD];      // node features fp32 (layer input / ping)
__device__ __half g_hph[NN * DD];    // projected features, half (edge gather)
__device__ float  g_ai[NN * HH];     // per-node att dot, dst half (fp32)
__device__ __half g_ajh[NN * HH];    // per-node att dot, src half (fp16)
__device__ int    g_deg[NN];         // zero at entry (re-zeroed by input GEMM)
__device__ int    g_rowptr[NN];      // after scatter: rowptr[n] == orig rowptr[n+1]
__device__ int    g_csrc[EE];        // CSR-by-dst: source node per slot

// ---------------- CSR build ----------------
__global__ void k_hist(const int* __restrict__ dst) {
    int e = blockIdx.x * blockDim.x + threadIdx.x;
    if (e < EE) atomicAdd(&g_deg[dst[e]], 1);
}

// single merged scan: each block redundantly computes its carry (sum of deg
// before its chunk), then does a local 1024-wide scan and writes rowptr.
__global__ void __launch_bounds__(1024) k_scan() {
    __shared__ int ws[32];
    __shared__ int red[32];
    int tidx = threadIdx.x;
    int lane = tidx & 31, w = tidx >> 5;
    int limit = blockIdx.x << 10;
    int acc = 0;
    for (int i = tidx; i < limit; i += 1024) acc += g_deg[i];
#pragma unroll
    for (int o = 16; o > 0; o >>= 1) acc += __shfl_xor_sync(0xffffffffu, acc, o);
    if (lane == 0) red[w] = acc;
    int i = limit + tidx;
    int x = (i < NN) ? g_deg[i] : 0;
    int v = x;
#pragma unroll
    for (int o = 1; o < 32; o <<= 1) {
        int t = __shfl_up_sync(0xffffffffu, v, o);
        if (lane >= o) v += t;
    }
    if (lane == 31) ws[w] = v;
    __syncthreads();
    if (w == 0) {
        int t = ws[lane];
#pragma unroll
        for (int o = 1; o < 32; o <<= 1) {
            int u = __shfl_up_sync(0xffffffffu, t, o);
            if (lane >= o) t += u;
        }
        ws[lane] = t;
        int r = red[lane];
#pragma unroll
        for (int o = 16; o > 0; o >>= 1) r += __shfl_xor_sync(0xffffffffu, r, o);
        if (lane == 0) red[0] = r;
    }
    __syncthreads();
    int carry = red[0];
    int off = (w > 0) ? ws[w - 1] : 0;
    if (i < NN) g_rowptr[i] = carry + off + v - x;   // exclusive global prefix
}

__global__ void k_scatter(const int* __restrict__ src, const int* __restrict__ dst) {
    int e = blockIdx.x * blockDim.x + threadIdx.x;
    if (e < EE) {
        int pos = atomicAdd(&g_rowptr[dst[e]], 1);
        g_csrc[pos] = src[e];
    }
}

// ---------------- split-fp16 tensor GEMM (packed-K Markidis) ----------------
// C = A@W + bias with ~fp32 precision: A=Ah+Al, W=Wh+Wl (fp16 splits);
// C = Ah*Wh + Al*Wh + Ah*Wl (+O(2^-22)). As=[Ah|Al] (64x128), Bs=[Wh;Wl] (128x64).
// Block 128 thr / 64 rows; warp tile m16 x n64. smem 36KB.
// att mode: writes half hp + fused per-head att dots ai (fp32) / aj (fp16).
// relu mode: writes fp32 Cf (input embedding) and zeroes g_deg for next call.
__device__ __forceinline__ uint32_t smem_u32(const void* p) {
    return (uint32_t)__cvta_generic_to_shared(p);
}

#define LDSM_X4(r0, r1, r2, r3, addr) \
    asm volatile("ldmatrix.sync.aligned.m8n8.x4.shared.b16 {%0,%1,%2,%3}, [%4];" \
        : "=r"(r0), "=r"(r1), "=r"(r2), "=r"(r3) : "r"(addr))

#define LDSM_X4_T(r0, r1, r2, r3, addr) \
    asm volatile("ldmatrix.sync.aligned.m8n8.x4.trans.shared.b16 {%0,%1,%2,%3}, [%4];" \
        : "=r"(r0), "=r"(r1), "=r"(r2), "=r"(r3) : "r"(addr))

#define MMA16816(c, a0, a1, a2, a3, b0, b1) \
    asm volatile("mma.sync.aligned.m16n8k16.row.col.f32.f16.f16.f32 " \
        "{%0,%1,%2,%3}, {%4,%5,%6,%7}, {%8,%9}, {%0,%1,%2,%3};" \
        : "+f"(c[0]), "+f"(c[1]), "+f"(c[2]), "+f"(c[3]) \
        : "r"(a0), "r"(a1), "r"(a2), "r"(a3), "r"(b0), "r"(b1))

#define SMSA 136  // As row stride in halves (128 + 8 pad)
#define SMSB 72   // Bs row stride in halves (64 + 8 pad)

__device__ __forceinline__ void split8(const float* v, __half* hi, __half* lo) {
#pragma unroll
    for (int q = 0; q < 8; q++) {
        __half h = __float2half_rn(v[q]);
        hi[q] = h;
        lo[q] = __float2half_rn(v[q] - __half2float(h));
    }
}

__global__ void __launch_bounds__(128) k_gemm_s(const float* __restrict__ A,
                                                const float* __restrict__ W,
                                                const float* __restrict__ bias,
                                                float* __restrict__ Cf,
                                                __half* __restrict__ Ch,
                                                int do_relu,
                                                const float* __restrict__ att) {
    __shared__ __half As[64 * SMSA];   // [Ah | Al]
    __shared__ __half Bs[128 * SMSB];  // [Wh ; Wl]
    int tid = threadIdx.x;
    int base = blockIdx.x * 64;
    if (do_relu) {                     // reset deg for the NEXT call's histogram
        int gz = blockIdx.x * 128 + tid;
        if (gz < NN) g_deg[gz] = 0;
    }
#pragma unroll
    for (int i = 0; i < 4; i++) {
        int chunk = tid + i * 128;            // 0..511
        int r = chunk >> 3, c = (chunk & 7) * 8;
        float wv[8];
        *(float4*)(wv)     = *(const float4*)(W + r * 64 + c);
        *(float4*)(wv + 4) = *(const float4*)(W + r * 64 + c + 4);
        __align__(16) __half wh[8], wl[8];
        split8(wv, wh, wl);
        *(uint4*)(Bs + r * SMSB + c)          = *(uint4*)wh;
        *(uint4*)(Bs + (64 + r) * SMSB + c)   = *(uint4*)wl;

        int gr = base + r;
        float av[8] = {0.f, 0.f, 0.f, 0.f, 0.f, 0.f, 0.f, 0.f};
        if (gr < NN) {
            *(float4*)(av)     = *(const float4*)(A + (size_t)gr * 64 + c);
            *(float4*)(av + 4) = *(const float4*)(A + (size_t)gr * 64 + c + 4);
        }
        __align__(16) __half ah[8], al[8];
        split8(av, ah, al);
        *(uint4*)(As + r * SMSA + c)        = *(uint4*)ah;
        *(uint4*)(As + r * SMSA + c + 64)   = *(uint4*)al;
    }
    __syncthreads();

    int warp = tid >> 5, lane = tid & 31;
    int m0 = warp * 16;
    float acc[8][4];
#pragma unroll
    for (int n = 0; n < 8; n++)
#pragma unroll
        for (int q = 0; q < 4; q++) acc[n][q] = 0.f;

    // preload all A fragments: ka 0..3 = Ah, 4..7 = Al
    uint32_t aA[8][4];
#pragma unroll
    for (int ka = 0; ka < 8; ka++) {
        int aoff = (m0 + (lane & 15)) * SMSA + ka * 16 + (lane >> 4) * 8;
        LDSM_X4(aA[ka][0], aA[ka][1], aA[ka][2], aA[ka][3], smem_u32(As + aoff));
    }

#pragma unroll
    for (int np = 0; np < 4; np++) {
        // b rows 0..3 = Wh: paired with Ah (term1) and Al (term2)
#pragma unroll
        for (int kk = 0; kk < 4; kk++) {
            uint32_t b0, b1, b2, b3;
            int boff = (kk * 16 + (lane & 15)) * SMSB + np * 16 + (lane >> 4) * 8;
            LDSM_X4_T(b0, b1, b2, b3, smem_u32(Bs + boff));
            MMA16816(acc[2 * np],     aA[kk][0], aA[kk][1], aA[kk][2], aA[kk][3], b0, b1);
            MMA16816(acc[2 * np + 1], aA[kk][0], aA[kk][1], aA[kk][2], aA[kk][3], b2, b3);
            MMA16816(acc[2 * np],     aA[kk + 4][0], aA[kk + 4][1], aA[kk + 4][2], aA[kk + 4][3], b0, b1);
            MMA16816(acc[2 * np + 1], aA[kk + 4][0], aA[kk + 4][1], aA[kk + 4][2], aA[kk + 4][3], b2, b3);
        }
        // b rows 4..7 = Wl: paired with Ah (term3)
#pragma unroll
        for (int kk = 0; kk < 4; kk++) {
            uint32_t b0, b1, b2, b3;
            int boff = ((kk + 4) * 16 + (lane & 15)) * SMSB + np * 16 + (lane >> 4) * 8;
            LDSM_X4_T(b0, b1, b2, b3, smem_u32(Bs + boff));
            MMA16816(acc[2 * np],     aA[kk][0], aA[kk][1], aA[kk][2], aA[kk][3], b0, b1);
            MMA16816(acc[2 * np + 1], aA[kk][0], aA[kk][1], aA[kk][2], aA[kk][3], b2, b3);
        }
    }

    int qr = lane >> 2, qc = (lane & 3) * 2;
    int r0 = base + m0 + qr, r1 = r0 + 8;
    if (att != nullptr) {
#pragma unroll
        for (int n = 0; n < 8; n++) {
            int col = n * 8 + qc;
            float2 bb = *(const float2*)(bias + col);
            float x0 = acc[n][0] + bb.x, y0 = acc[n][1] + bb.y;
            float x1 = acc[n][2] + bb.x, y1 = acc[n][3] + bb.y;
            // head index == n; this thread covers cols qc, qc+1 of head n
            float ci0 = att[n * 16 + qc],     ci1 = att[n * 16 + qc + 1];
            float cj0 = att[n * 16 + 8 + qc], cj1 = att[n * 16 + 8 + qc + 1];
            float pi0 = x0 * ci0 + y0 * ci1, pj0 = x0 * cj0 + y0 * cj1;
            float pi1 = x1 * ci0 + y1 * ci1, pj1 = x1 * cj0 + y1 * cj1;
            pi0 += __shfl_xor_sync(0xffffffffu, pi0, 1);
            pi0 += __shfl_xor_sync(0xffffffffu, pi0, 2);
            pj0 += __shfl_xor_sync(0xffffffffu, pj0, 1);
            pj0 += __shfl_xor_sync(0xffffffffu, pj0, 2);
            pi1 += __shfl_xor_sync(0xffffffffu, pi1, 1);
            pi1 += __shfl_xor_sync(0xffffffffu, pi1, 2);
            pj1 += __shfl_xor_sync(0xffffffffu, pj1, 1);
            pj1 += __shfl_xor_sync(0xffffffffu, pj1, 2);
            if (r0 < NN) {
                *(__half2*)(Ch + (size_t)r0 * 64 + col) = __floats2half2_rn(x0, y0);
                if ((lane & 3) == 0) {
                    g_ai[r0 * 8 + n]  = pi0;
                    g_ajh[r0 * 8 + n] = __float2half(pj0);
                }
            }
            if (r1 < NN) {
                *(__half2*)(Ch + (size_t)r1 * 64 + col) = __floats2half2_rn(x1, y1);
                if ((lane & 3) == 0) {
                    g_ai[r1 * 8 + n]  = pi1;
                    g_ajh[r1 * 8 + n] = __float2half(pj1);
                }
            }
        }
    } else {
#pragma unroll
        for (int n = 0; n < 8; n++) {
            int col = n * 8 + qc;
            float2 bb = *(const float2*)(bias + col);
            float x0 = acc[n][0] + bb.x, y0 = acc[n][1] + bb.y;
            float x1 = acc[n][2] + bb.x, y1 = acc[n][3] + bb.y;
            if (do_relu) {
                x0 = fmaxf(x0, 0.f); y0 = fmaxf(y0, 0.f);
                x1 = fmaxf(x1, 0.f); y1 = fmaxf(y1, 0.f);
            }
            if (r0 < NN) *(float2*)(Cf + (size_t)r0 * 64 + col) = make_float2(x0, y0);
            if (r1 < NN) *(float2*)(Cf + (size_t)r1 * 64 + col) = make_float2(x1, y1);
        }
    }
}

// ---------------- fused edge softmax + aggregation + ELU + LayerNorm ----------------
// One warp per destination node. Lane l owns cols (2l,2l+1), head h = l>>2.
// Inner loop processes 8 edges (2 quad-groups) per iteration with straight-line
// scalars: 8 independent hp gathers + 2 aj loads in flight; aj prefetched one
// full iteration ahead. Out-of-range edges get weight 0 (pre is 0-padded).
__global__ void __launch_bounds__(256) k_edge(const float* __restrict__ ob,
                                              const float* __restrict__ lg,
                                              const float* __restrict__ lb,
                                              float* __restrict__ out) {
    int n = (blockIdx.x * blockDim.x + threadIdx.x) >> 5;
    int lane = threadIdx.x & 31;
    if (n >= NN) return;
    // post-scatter rowptr is shifted: rp[n] == original rowptr[n+1]
    int e0 = (n == 0) ? 0 : __ldg(&g_rowptr[n - 1]);
    int e1 = __ldg(&g_rowptr[n]);
    int h = lane >> 2;
    int sub = lane & 3;        // my edge slot within a group
    int qb = lane & ~3;        // quad base lane (holds my head's 4 edge weights)
    float aih = __ldg(&g_ai[n * 8 + h]);

    float s = 0.f, ax = 0.f, ay = 0.f;
    const __half2* hp2 = (const __half2*)g_hph;
    for (int cb = e0; cb < e1; cb += 32) {
        int idx = cb + lane;
        int pre = (idx < e1) ? __ldg(&g_csrc[idx]) : 0;
        int cnt = min(32, e1 - cb);
        int ng = (cnt + 3) >> 2;
        // prefetch aj for groups 0 and 1
        int pA = __shfl_sync(0xffffffffu, pre, sub);
        int pB = __shfl_sync(0xffffffffu, pre, min(4 + sub, 31));
        __half ajA = __ldg(&g_ajh[pA * 8 + h]);
        __half ajB = __ldg(&g_ajh[pB * 8 + h]);
        for (int g = 0; g < ng; g += 2) {
            int eA = g * 4 + sub, eB = eA + 4;
            float aAv = aih + __half2float(ajA);
            float aBv = aih + __half2float(ajB);
            // prefetch aj for groups g+2, g+3
            {
                int iA = min(eA + 8, 31), iB = min(eA + 12, 31);
                int nA = __shfl_sync(0xffffffffu, pre, iA);
                int nB = __shfl_sync(0xffffffffu, pre, iB);
                ajA = __ldg(&g_ajh[nA * 8 + h]);
                ajB = __ldg(&g_ajh[nB * 8 + h]);
            }
            aAv = fmaxf(aAv, 0.2f * aAv);     // leaky_relu(0.2)
            aBv = fmaxf(aBv, 0.2f * aBv);
            float wA = (eA < cnt) ? __expf(aAv) : 0.f;
            float wB = (eB < cnt) ? __expf(aBv) : 0.f;
            // 8 hp gathers, all independent (edges g*4 .. g*4+7, indices <= 31)
            int s0 = __shfl_sync(0xffffffffu, pre, g * 4);
            int s1 = __shfl_sync(0xffffffffu, pre, g * 4 + 1);
            int s2 = __shfl_sync(0xffffffffu, pre, g * 4 + 2);
            int s3 = __shfl_sync(0xffffffffu, pre, g * 4 + 3);
            int s4 = __shfl_sync(0xffffffffu, pre, min(g * 4 + 4, 31));
            int s5 = __shfl_sync(0xffffffffu, pre, min(g * 4 + 5, 31));
            int s6 = __shfl_sync(0xffffffffu, pre, min(g * 4 + 6, 31));
            int s7 = __shfl_sync(0xffffffffu, pre, min(g * 4 + 7, 31));
            float2 v0 = __half22float2(__ldg(&hp2[(unsigned)(s0 * 32 + lane)]));
            float2 v1 = __half22float2(__ldg(&hp2[(unsigned)(s1 * 32 + lane)]));
            float2 v2 = __half22float2(__ldg(&hp2[(unsigned)(s2 * 32 + lane)]));
            float2 v3 = __half22float2(__ldg(&hp2[(unsigned)(s3 * 32 + lane)]));
            float2 v4 = __half22float2(__ldg(&hp2[(unsigned)(s4 * 32 + lane)]));
            float2 v5 = __half22float2(__ldg(&hp2[(unsigned)(s5 * 32 + lane)]));
            float2 v6 = __half22float2(__ldg(&hp2[(unsigned)(s6 * 32 + lane)]));
            float2 v7 = __half22float2(__ldg(&hp2[(unsigned)(s7 * 32 + lane)]));
            float w0 = __shfl_sync(0xffffffffu, wA, qb);
            float w1 = __shfl_sync(0xffffffffu, wA, qb + 1);
            float w2 = __shfl_sync(0xffffffffu, wA, qb + 2);
            float w3 = __shfl_sync(0xffffffffu, wA, qb + 3);
            float w4 = __shfl_sync(0xffffffffu, wB, qb);
            float w5 = __shfl_sync(0xffffffffu, wB, qb + 1);
            float w6 = __shfl_sync(0xffffffffu, wB, qb + 2);
            float w7 = __shfl_sync(0xffffffffu, wB, qb + 3);
            s += (w0 + w1 + w2 + w3) + (w4 + w5 + w6 + w7);
            ax += v0.x * w0 + v1.x * w1 + v2.x * w2 + v3.x * w3
                + v4.x * w4 + v5.x * w5 + v6.x * w6 + v7.x * w7;
            ay += v0.y * w0 + v1.y * w1 + v2.y * w2 + v3.y * w3
                + v4.y * w4 + v5.y * w5 + v6.y * w6 + v7.y * w7;
        }
    }

    float inv = 1.f / (s + 1e-16f);
    float vx = ax * inv + ob[2 * lane];
    float vy = ay * inv + ob[2 * lane + 1];
    vx = vx > 0.f ? vx : expm1f(vx);          // ELU
    vy = vy > 0.f ? vy : expm1f(vy);

    float sum = vx + vy, sq = vx * vx + vy * vy;
#pragma unroll
    for (int o = 16; o > 0; o >>= 1) {
        sum += __shfl_xor_sync(0xffffffffu, sum, o);
        sq  += __shfl_xor_sync(0xffffffffu, sq, o);
    }
    float mu = sum * (1.f / 64.f);
    float var = sq * (1.f / 64.f) - mu * mu;
    float rstd = rsqrtf(var + 1e-5f);
    float2 o2;
    o2.x = (vx - mu) * rstd * lg[2 * lane] + lb[2 * lane];
    o2.y = (vy - mu) * rstd * lg[2 * lane + 1] + lb[2 * lane + 1];
    ((float2*)out)[(size_t)n * 32 + lane] = o2;
}

// ---------------- launch ----------------
extern "C" void kernel_launch(void* const* d_in, const int* in_sizes, int n_in,
                              void* d_out, int out_size) {
    const float* x        = (const float*)d_in[0];
    const int*   ei       = (const int*)  d_in[1];
    const float* W_in     = (const float*)d_in[2];
    const float* b_in     = (const float*)d_in[3];
    const float* lin_w    = (const float*)d_in[4];
    const float* lin_b    = (const float*)d_in[5];
    const float* att      = (const float*)d_in[6];
    const float* out_bias = (const float*)d_in[7];
    const float* ln_g     = (const float*)d_in[8];
    const float* ln_b     = (const float*)d_in[9];
    float* out = (float*)d_out;
    const int* srcp = ei;        // edge_index[0]
    const int* dstp = ei + EE;   // edge_index[1]
    (void)n_in; (void)in_sizes; (void)out_size;

    void* p;
    cudaGetSymbolAddress(&p, g_h);    float*  ph   = (float*)p;
    cudaGetSymbolAddress(&p, g_hph);  __half* phph = (__half*)p;

    // CSR by dst (g_deg is zero at entry: initially zero-filled, and the input
    // GEMM of every call re-zeroes it after k_scan's last read)
    k_hist   <<<(EE + 255) / 256, 256>>>(dstp);
    k_scan   <<<(NN + 1023) / 1024, 1024>>>();
    k_scatter<<<(EE + 255) / 256, 256>>>(srcp, dstp);

    int gblocks = (NN + 63) / 64;
    // input embedding: h = relu(x @ W_in + b_in), fp32 (also zeroes g_deg)
    k_gemm_s<<<gblocks, 128>>>(x, W_in, b_in, ph, nullptr, 1, nullptr);

    for (int l = 0; l < 5; l++) {
        k_gemm_s<<<gblocks, 128>>>(ph, lin_w + l * 64 * 64, lin_b + l * 64,
                                   nullptr, phph, 0, att + l * 128);
        k_edge<<<(NN + 7) / 8, 256>>>(out_bias + l * 64, ln_g + l * 64, ln_b + l * 64,
                                      (l == 4) ? out : ph);
    }
}